// round 14
// baseline (speedup 1.0000x reference)
#include <cuda_runtime.h>
#include <cuda_fp16.h>
#include <math.h>

#define NB   1024
#define NR   2336
#define NK   2
#define RPC  1168                   // routes per CTA (half of NR)
// Cin = 4, Cout = 16 (fixed)

__device__ float g_cls[NB * NK];
// Pre-converted fp16 W: per (k,r,q): 16 halfs (i=0..3 x out-in-quad 0..3) = 32 B
// index: ((k*NR + r)*4 + q) * 2 uint4
__device__ uint4 g_W16[(size_t)NK * NR * 4 * 2];

// ---------------------------------------------------------------------------
// W conversion kernel: f32 -> packed fp16, quad-contiguous layout.
// ---------------------------------------------------------------------------
__global__ void conv_w_kernel(const float4* __restrict__ W4)
{
    int idx = blockIdx.x * blockDim.x + threadIdx.x;   // (k*NR+r)*4 + q
    if (idx < NK * NR * 4) {
        int q  = idx & 3;
        int kr = idx >> 2;
        const float4* wp = W4 + (size_t)kr * 16 + q;
        float4 w0 = __ldg(wp);      float4 w1 = __ldg(wp + 4);
        float4 w2 = __ldg(wp + 8);  float4 w3 = __ldg(wp + 12);
        __half2 h0 = __floats2half2_rn(w0.x, w0.y), h1 = __floats2half2_rn(w0.z, w0.w);
        __half2 h2 = __floats2half2_rn(w1.x, w1.y), h3 = __floats2half2_rn(w1.z, w1.w);
        __half2 h4 = __floats2half2_rn(w2.x, w2.y), h5 = __floats2half2_rn(w2.z, w2.w);
        __half2 h6 = __floats2half2_rn(w3.x, w3.y), h7 = __floats2half2_rn(w3.z, w3.w);
        uint4 p0, p1;
        p0.x = *(unsigned*)&h0; p0.y = *(unsigned*)&h1;
        p0.z = *(unsigned*)&h2; p0.w = *(unsigned*)&h3;
        p1.x = *(unsigned*)&h4; p1.y = *(unsigned*)&h5;
        p1.z = *(unsigned*)&h6; p1.w = *(unsigned*)&h7;
        g_W16[(size_t)idx * 2]     = p0;
        g_W16[(size_t)idx * 2 + 1] = p1;
    }
}

// ---------------------------------------------------------------------------
// Cluster-2 route-split fused kernel.
// Cluster = 2 CTAs, same (k, 4 batches); rank owns routes [rank*RPC, +RPC).
// u_ji half-tiles live in smem (fp16 half-planes); the 3 route-wide
// reductions exchange 17 floats/batch via DSMEM (mapa + ld.shared::cluster).
// ---------------------------------------------------------------------------
// per-batch half-tile: planeA (quads 0-1, 16 B/route) | 64 B pad | planeB
#define PBH         18752           // planeB offset inside tile (==64 mod 128)
#define TILE        37440
#define BS_OFF      (4*TILE)        // 149760 : fp32 logits, 4 x RPC floats
#define RED_OFF     (BS_OFF + 4*RPC*4)  // 168448 : 4096 B scratch (red4 / red)
#define EXS1_OFF    (RED_OFF + 4096)    // 172544 : 4 x 20 floats
#define EXI0_OFF    (EXS1_OFF + 320)    // 172864
#define EXI1_OFF    (EXI0_OFF + 320)    // 173184
#define V4S_OFF     (EXI1_OFF + 320)    // 173504 : 16 float4 (4 per batch)
#define CLS_OFF     (V4S_OFF + 256)     // 173760 : 4 floats
#define SMEM_BYTES  (CLS_OFF + 16)      // 173776 -> 1 CTA/SM

// ---- PTX helpers ----------------------------------------------------------
__device__ __forceinline__ unsigned smem_u32(const void* p) {
    unsigned a;
    asm("{ .reg .u64 t; cvta.to.shared.u64 t, %1; cvt.u32.u64 %0, t; }"
        : "=r"(a) : "l"(p));
    return a;
}
__device__ __forceinline__ unsigned ctarank() {
    unsigned r; asm("mov.u32 %0, %%cluster_ctarank;" : "=r"(r)); return r;
}
__device__ __forceinline__ float ld_peer(unsigned my_addr, unsigned peer_rank) {
    float v;
    asm volatile("{\n\t.reg .b32 ra;\n\t"
        "mapa.shared::cluster.u32 ra, %1, %2;\n\t"
        "ld.shared::cluster.f32 %0, [ra];\n\t}"
        : "=f"(v) : "r"(my_addr), "r"(peer_rank));
    return v;
}
#define CLUSTER_SYNC() do { \
    asm volatile("barrier.cluster.arrive.aligned;" ::: "memory"); \
    asm volatile("barrier.cluster.wait.aligned;"  ::: "memory"); } while (0)

// ---------------------------------------------------------------------------
__device__ __forceinline__ void squash_from(const float* tot, float cn,
                                            float4* v4out, float* clsout)
{
    float s[16];
#pragma unroll
    for (int o = 0; o < 16; o++) s[o] = tot[o] * cn;
    float n = 0.f;
#pragma unroll
    for (int o = 0; o < 16; o++) n += s[o] * s[o];
    // squash: v = (n/(1+n)) * s / sqrt(n);  |v| = n/(1+n)
    float f = n / ((1.f + n) * sqrtf(fmaxf(n, 1e-30f)));
#pragma unroll
    for (int qq = 0; qq < 4; qq++)
        v4out[qq] = make_float4(f*s[qq*4+0], f*s[qq*4+1], f*s[qq*4+2], f*s[qq*4+3]);
    *clsout = n / (1.f + n);
}

#define XOR_RED4(a, off) do { \
    a.x += __shfl_xor_sync(0xffffffffu, a.x, off); \
    a.y += __shfl_xor_sync(0xffffffffu, a.y, off); \
    a.z += __shfl_xor_sync(0xffffffffu, a.z, off); \
    a.w += __shfl_xor_sync(0xffffffffu, a.w, off); } while (0)

#define H2F2(dst, i, hw) do { \
    float2 _f = __half22float2(*reinterpret_cast<const __half2*>(&(hw))); \
    dst[i] = _f.x; dst[(i)+1] = _f.y; } while (0)

// one batch's quad projection + accumulate + fp16 store
__device__ __forceinline__ void proj_one(const float w[16], float4 uu,
                                         float4& acc, uint2* dst, int rl)
{
    float4 o;
    o.x = fmaf(uu.x,w[0], fmaf(uu.y,w[4], fmaf(uu.z,w[8],  uu.w*w[12])));
    o.y = fmaf(uu.x,w[1], fmaf(uu.y,w[5], fmaf(uu.z,w[9],  uu.w*w[13])));
    o.z = fmaf(uu.x,w[2], fmaf(uu.y,w[6], fmaf(uu.z,w[10], uu.w*w[14])));
    o.w = fmaf(uu.x,w[3], fmaf(uu.y,w[7], fmaf(uu.z,w[11], uu.w*w[15])));
    acc.x += o.x; acc.y += o.y; acc.z += o.z; acc.w += o.w;
    __half2 hA = __floats2half2_rn(o.x, o.y);
    __half2 hB = __floats2half2_rn(o.z, o.w);
    uint2 hv;
    hv.x = *reinterpret_cast<unsigned*>(&hA);
    hv.y = *reinterpret_cast<unsigned*>(&hB);
    dst[(size_t)rl * 2] = hv;
}

#define PROJ4(rl) do { \
    const uint4* wp = w16 + ((size_t)(rl) * 4 + q) * 2; \
    uint4 hw0 = __ldg(wp); uint4 hw1 = __ldg(wp + 1); \
    float4 uu0 = __ldg(ub0 + (rl)); float4 uu1 = __ldg(ub1 + (rl)); \
    float4 uu2 = __ldg(ub2 + (rl)); float4 uu3 = __ldg(ub3 + (rl)); \
    float w[16]; \
    H2F2(w, 0,  hw0.x); H2F2(w, 2,  hw0.y); \
    H2F2(w, 4,  hw0.z); H2F2(w, 6,  hw0.w); \
    H2F2(w, 8,  hw1.x); H2F2(w, 10, hw1.y); \
    H2F2(w, 12, hw1.z); H2F2(w, 14, hw1.w); \
    proj_one(w, uu0, acc0, dst0, (rl)); \
    proj_one(w, uu1, acc1, dst1, (rl)); \
    proj_one(w, uu2, acc2, dst2, (rl)); \
    proj_one(w, uu3, acc3, dst3, (rl)); } while (0)

__global__ void __launch_bounds__(512, 1) __cluster_dims__(2, 1, 1)
caps_fused_kernel(const float4* __restrict__ u4)   // u: [b*NR + r] float4
{
    extern __shared__ char smb[];
    const unsigned sbase = smem_u32(smb);
    const int t = threadIdx.x;
    const int lane = t & 31, warp = t >> 5;
    const unsigned rank = ctarank();
    const unsigned peer = rank ^ 1u;
    const int pid = blockIdx.x >> 1;         // cluster id
    const int k   = pid & 1;
    const int b0  = (pid >> 1) * 4;          // batches b0..b0+3

    const float4* ub0 = u4 + (size_t)(b0 + 0) * NR + rank * RPC;
    const float4* ub1 = u4 + (size_t)(b0 + 1) * NR + rank * RPC;
    const float4* ub2 = u4 + (size_t)(b0 + 2) * NR + rank * RPC;
    const float4* ub3 = u4 + (size_t)(b0 + 3) * NR + rank * RPC;
    const uint4*  w16 = g_W16 + ((size_t)k * NR + rank * RPC) * 8;

    float4* red4 = (float4*)(smb + RED_OFF);     // sweep-1 partials
    float*  redf = (float*)(smb + RED_OFF);      // phase-2 partials / totals
    float*  v4sf = (float*)(smb + V4S_OFF);
    float4* v4s  = (float4*)(smb + V4S_OFF);     // [batch*4 + qq]
    float*  cls  = (float*)(smb + CLS_OFF);

    // --- Phase 1: projection of this CTA's route half into 4 fp16 tiles ---
    const int q = t & 3;                     // out-quad
    const int g = t >> 2;                    // route-in-chunk 0..127
    uint2* dst0 = (uint2*)(smb + 0*TILE + (q < 2 ? 0 : PBH)) + (q & 1);
    uint2* dst1 = (uint2*)(smb + 1*TILE + (q < 2 ? 0 : PBH)) + (q & 1);
    uint2* dst2 = (uint2*)(smb + 2*TILE + (q < 2 ? 0 : PBH)) + (q & 1);
    uint2* dst3 = (uint2*)(smb + 3*TILE + (q < 2 ? 0 : PBH)) + (q & 1);

    float4 acc0 = make_float4(0.f,0.f,0.f,0.f);
    float4 acc1 = acc0, acc2 = acc0, acc3 = acc0;
#pragma unroll 2
    for (int c = 0; c < 9; c++) {            // 9*128 = 1152 routes
        int rl = c * 128 + g;
        PROJ4(rl);
    }
    if (g < 16) {                            // tail: 1152..1167
        int rl = 1152 + g;
        PROJ4(rl);
    }

    // --- Sweep-1 reduction (uniform c = 1/NR): local -> DSMEM -> squash ---
    XOR_RED4(acc0, 4); XOR_RED4(acc0, 8); XOR_RED4(acc0, 16);
    XOR_RED4(acc1, 4); XOR_RED4(acc1, 8); XOR_RED4(acc1, 16);
    XOR_RED4(acc2, 4); XOR_RED4(acc2, 8); XOR_RED4(acc2, 16);
    XOR_RED4(acc3, 4); XOR_RED4(acc3, 8); XOR_RED4(acc3, 16);
    if (lane < 4) {                          // red4[(batch*16 + warp)*4 + q]
        red4[(0*16 + warp)*4 + lane] = acc0;
        red4[(1*16 + warp)*4 + lane] = acc1;
        red4[(2*16 + warp)*4 + lane] = acc2;
        red4[(3*16 + warp)*4 + lane] = acc3;
    }
    __syncthreads();
    if (warp < 4) {                          // batch = warp
        float4 e = red4[warp*64 + lane];
        float4 e2 = red4[warp*64 + 32 + lane];
        e.x += e2.x; e.y += e2.y; e.z += e2.z; e.w += e2.w;
        XOR_RED4(e, 4); XOR_RED4(e, 8); XOR_RED4(e, 16);
        if (lane < 4) {                      // quad q = lane totals (local half)
            float* ex = (float*)(smb + EXS1_OFF) + warp*20 + lane*4;
            ex[0] = e.x; ex[1] = e.y; ex[2] = e.z; ex[3] = e.w;
        }
    }
    __syncthreads();
    CLUSTER_SYNC();                          // peer's EXS1 visible
    if (warp < 4 && lane < 16) {
        unsigned exa = sbase + EXS1_OFF + (warp*20 + lane)*4;
        float own = *((float*)(smb + EXS1_OFF) + warp*20 + lane);
        float tot = own + ld_peer(exa, peer);
        redf[warp*20 + lane] = tot;          // red4 reads are done; reuse
    }
    __syncwarp();
    if (warp < 4 && lane == 0)
        squash_from(redf + warp*20, 1.f / (float)NR, v4s + warp*4, cls + warp);
    __syncthreads();

    // --- Phase 2: two fused (b-update + softmax s-sweep) iterations ---
    // 4 warps per batch; thread-per-route over this CTA's half.
    const int bloc = warp >> 2;              // batch 0..3
    const int tt   = t & 127;
    const uint4* pA = (const uint4*)(smb + bloc*TILE);
    const uint4* pB = (const uint4*)(smb + bloc*TILE + PBH);
    float* bs = (float*)(smb + BS_OFF) + bloc * RPC;

#pragma unroll
    for (int it = 0; it < 2; it++) {
        const int exoff = it ? EXI1_OFF : EXI0_OFF;
        float vv[16];
#pragma unroll
        for (int o = 0; o < 16; o++) vv[o] = v4sf[bloc*16 + o];
        float a[17];
#pragma unroll
        for (int o = 0; o < 17; o++) a[o] = 0.f;

#pragma unroll 2
        for (int r = tt; r < RPC; r += 128) {
            uint4 ha = pA[r];                // quads 0-1 (8 halfs)
            uint4 hb = pB[r];                // quads 2-3
            float x[16];
            H2F2(x, 0,  ha.x); H2F2(x, 2,  ha.y);
            H2F2(x, 4,  ha.z); H2F2(x, 6,  ha.w);
            H2F2(x, 8,  hb.x); H2F2(x, 10, hb.y);
            H2F2(x, 12, hb.z); H2F2(x, 14, hb.w);
            float d = x[0] * vv[0];
#pragma unroll
            for (int o = 1; o < 16; o++) d = fmaf(x[o], vv[o], d);
            float bn;
            if (it == 0) { bn = d; bs[r] = d; }
            else         { bn = bs[r] + d; }
            float e = __expf(bn);            // logits bounded, no max-shift
            a[16] += e;                      // Z
#pragma unroll
            for (int o = 0; o < 16; o++) a[o] = fmaf(e, x[o], a[o]);
        }

        // intra-warp reduce of 17 values
#pragma unroll
        for (int off = 1; off < 32; off <<= 1)
#pragma unroll
            for (int o = 0; o < 17; o++)
                a[o] += __shfl_xor_sync(0xffffffffu, a[o], off);
        if (lane == 0) {
            float* rp = redf + (bloc*4 + (warp & 3)) * 20;
#pragma unroll
            for (int o = 0; o < 17; o++) rp[o] = a[o];
        }
        __syncthreads();

        float own = 0.f;
        if (warp < 4 && lane < 17) {         // combine 4 warp-partials, batch=warp
#pragma unroll
            for (int w4 = 0; w4 < 4; w4++)
                own += redf[(warp*4 + w4)*20 + lane];
            *((float*)(smb + exoff) + warp*20 + lane) = own;
        }
        __syncthreads();
        CLUSTER_SYNC();                      // peer's EX slot visible
        if (warp < 4 && lane < 17) {
            unsigned exa = sbase + exoff + (warp*20 + lane)*4;
            float tot = own + ld_peer(exa, peer);
            redf[warp*20 + lane] = tot;
        }
        __syncwarp();
        if (warp < 4 && lane == 0)
            squash_from(redf + warp*20, 1.f / redf[warp*20 + 16],
                        v4s + warp*4, cls + warp);
        __syncthreads();
    }

    if (rank == 0 && t < 4)
        g_cls[(size_t)(b0 + t) * 2 + k] = cls[t];
    CLUSTER_SYNC();                          // keep smem alive for peer reads
}

// ---------------------------------------------------------------------------
// Final softmax over K=2 classes per batch
// ---------------------------------------------------------------------------
__global__ void caps_softmax_kernel(float* __restrict__ out)
{
    int b = blockIdx.x * blockDim.x + threadIdx.x;
    if (b < NB) {
        float c0 = g_cls[2*b], c1 = g_cls[2*b + 1];
        float m  = fmaxf(c0, c1);
        float e0 = expf(c0 - m), e1 = expf(c1 - m);
        float inv = 1.f / (e0 + e1);
        out[2*b]     = e0 * inv;
        out[2*b + 1] = e1 * inv;
    }
}

// ---------------------------------------------------------------------------
extern "C" void kernel_launch(void* const* d_in, const int* in_sizes, int n_in,
                              void* d_out, int out_size)
{
    const float4* u4 = (const float4*)d_in[0];   // u: [1024,2336,4] f32
    const float4* W4 = (const float4*)d_in[1];   // W: [2,2336,4,16] f32
    (void)in_sizes; (void)n_in; (void)out_size;

    cudaFuncSetAttribute(caps_fused_kernel,
                         cudaFuncAttributeMaxDynamicSharedMemorySize, SMEM_BYTES);

    conv_w_kernel<<<(NK * NR * 4 + 255) / 256, 256>>>(W4);
    caps_fused_kernel<<<NB, 512, SMEM_BYTES>>>(u4);   // 1024 CTAs, cluster 2
    caps_softmax_kernel<<<(NB + 255) / 256, 256>>>((float*)d_out);
}